// round 2
// baseline (speedup 1.0000x reference)
#include <cuda_runtime.h>
#include <cstdint>

// StochasticPool2d: x (16,96,224,224) f32, 2x2 non-overlapping windows.
// Reference: jax.random.categorical(key(42), window_vals) via Gumbel-max with
// threefry-2x32 (partitionable counter mode), sampled value written out.
//
// Shapes:
//   B=16 C=96 H=224 W=224  -> OH=OW=112
//   N_gumbel = 16*96*112*112*4 = 77,070,336
//   N_windows = 19,267,584 ; threads = N_windows/2 = 9,633,792 = 37632*256

static constexpr uint32_t TF_K1 = 42u;
static constexpr uint32_t TF_K2 = 0x1BD11BDAu ^ 0u ^ 42u;  // ks[2]

__device__ __forceinline__ uint32_t rotl32(uint32_t x, int d) {
    return __funnelshift_l(x, x, d);
}

// threefry2x32 with key=(0,42), counter=(hi=0, lo=n); returns out0 ^ out1
// (jax partitionable 32-bit random_bits combine).
__device__ __forceinline__ uint32_t threefry_bits(uint32_t n) {
    uint32_t x0 = 0u;        // counter_hi + ks[0] (both 0)
    uint32_t x1 = n + TF_K1; // counter_lo + ks[1]

#define TF_ROUND(r) { x0 += x1; x1 = rotl32(x1, (r)); x1 ^= x0; }
    // group 0 (rot set A)
    TF_ROUND(13) TF_ROUND(15) TF_ROUND(26) TF_ROUND(6)
    x0 += TF_K1;        x1 += TF_K2 + 1u;
    // group 1 (rot set B)
    TF_ROUND(17) TF_ROUND(29) TF_ROUND(16) TF_ROUND(24)
    x0 += TF_K2;        x1 += 0u + 2u;
    // group 2 (A)
    TF_ROUND(13) TF_ROUND(15) TF_ROUND(26) TF_ROUND(6)
    /* x0 += ks[0]=0 */ x1 += TF_K1 + 3u;
    // group 3 (B)
    TF_ROUND(17) TF_ROUND(29) TF_ROUND(16) TF_ROUND(24)
    x0 += TF_K1;        x1 += TF_K2 + 4u;
    // group 4 (A)
    TF_ROUND(13) TF_ROUND(15) TF_ROUND(26) TF_ROUND(6)
    x0 += TF_K2;        x1 += 0u + 5u;
#undef TF_ROUND
    return x0 ^ x1;
}

// bits -> uniform(tiny,1) -> gumbel, matching jax/_src/random.py _uniform+_gumbel
// in float32. u = max(tiny, f*(1-tiny)+tiny) == max(tiny, f) exactly in f32.
__device__ __forceinline__ float gumbel32(uint32_t bits) {
    float f = __uint_as_float((bits >> 9) | 0x3f800000u) - 1.0f;
    float u = fmaxf(f, 1.17549435e-38f);
    return -logf(-logf(u));   // logf == __nv_logf == XLA's f32 log
}

// argmax_k(g_k + v_k), first-max tie-break (matches jnp.argmax), return v.
__device__ __forceinline__ float pick4(float v0, float v1, float v2, float v3,
                                       const float* g) {
    float s0 = g[0] + v0, s1 = g[1] + v1, s2 = g[2] + v2, s3 = g[3] + v3;
    float best = s0, val = v0;
    if (s1 > best) { best = s1; val = v1; }
    if (s2 > best) { best = s2; val = v2; }
    if (s3 > best) { best = s3; val = v3; }
    return val;
}

__global__ void __launch_bounds__(256)
stochpool_kernel(const float* __restrict__ x, float* __restrict__ out) {
    uint32_t i = blockIdx.x * 256u + threadIdx.x;
    if (i >= 9633792u) return;

    // Thread i handles windows w0=2i, w1=2i+1 (adjacent in ow; OW=112 even so
    // a pair never straddles a row/channel boundary).
    uint32_t owp = i % 56u;          // pair index along ow (ow = 2*owp, 2*owp+1)
    uint32_t t   = i / 56u;
    uint32_t oh  = t % 112u;
    uint32_t bc  = t / 112u;         // b*96 + c

    // Input: rows 2*oh and 2*oh+1, cols 4*owp..4*owp+3  (float4 aligned)
    uint32_t in_base = (bc * 224u + 2u * oh) * 224u + 4u * owp;
    float4 r0 = *reinterpret_cast<const float4*>(x + in_base);
    float4 r1 = *reinterpret_cast<const float4*>(x + in_base + 224u);

    // Gumbel counters: window w uses linear gumbel indices 4w..4w+3,
    // so this thread consumes counters 8i..8i+7.
    uint32_t cbase = 8u * i;
    float g[8];
#pragma unroll
    for (int k = 0; k < 8; k++)
        g[k] = gumbel32(threefry_bits(cbase + (uint32_t)k));

    // window layout: k = kh*2+kw -> (r0.x, r0.y, r1.x, r1.y) for window 0
    float o0 = pick4(r0.x, r0.y, r1.x, r1.y, g);
    float o1 = pick4(r0.z, r0.w, r1.z, r1.w, g + 4);

    uint32_t out_base = (bc * 112u + oh) * 112u + 2u * owp;
    *reinterpret_cast<float2*>(out + out_base) = make_float2(o0, o1);
}

extern "C" void kernel_launch(void* const* d_in, const int* in_sizes, int n_in,
                              void* d_out, int out_size) {
    const float* x = (const float*)d_in[0];
    float* out = (float*)d_out;
    (void)in_sizes; (void)n_in; (void)out_size;
    stochpool_kernel<<<37632, 256>>>(x, out);
}

// round 6
// speedup vs baseline: 1.1577x; 1.1577x over previous
#include <cuda_runtime.h>
#include <cstdint>

// StochasticPool2d: x (16,96,224,224) f32, 2x2 non-overlapping windows.
// Reference: jax.random.categorical(key(42), window_vals) == Gumbel-max with
// threefry-2x32 (partitionable counter mode); output = sampled window value.
//
// B=16 C=96 H=224 W=224 -> OH=OW=112
// N_windows = 19,267,584 ; threads = N_windows/2 = 9,633,792 = 37632*256 exactly.
//
// Strategy: threefry is irreducible (bit-exact requirement). The two precise
// logf per gumbel are replaced by __logf (MUFU.LG2) in a fast path; a
// conservative error bound on the top1-top2 margin guarantees the argmax
// matches the exact computation; ambiguous windows (~0.4%) fall back to the
// bit-exact precise-logf path.

static constexpr uint32_t TF_K1 = 42u;
static constexpr uint32_t TF_K2 = 0x1BD11BDAu ^ 0u ^ 42u;  // ks[2]

__device__ __forceinline__ uint32_t rotl32(uint32_t x, int d) {
    return __funnelshift_l(x, x, d);
}

// threefry2x32, key=(0,42), counter=(0, n); returns out0 ^ out1.
__device__ __forceinline__ uint32_t threefry_bits(uint32_t n) {
    uint32_t x0 = 0u;        // counter_hi + ks[0] (both 0)
    uint32_t x1 = n + TF_K1; // counter_lo + ks[1]
#define TF_ROUND(r) { x0 += x1; x1 = rotl32(x1, (r)); x1 ^= x0; }
    TF_ROUND(13) TF_ROUND(15) TF_ROUND(26) TF_ROUND(6)
    x0 += TF_K1;        x1 += TF_K2 + 1u;
    TF_ROUND(17) TF_ROUND(29) TF_ROUND(16) TF_ROUND(24)
    x0 += TF_K2;        x1 += 0u + 2u;
    TF_ROUND(13) TF_ROUND(15) TF_ROUND(26) TF_ROUND(6)
    /* ks[0]=0 */       x1 += TF_K1 + 3u;
    TF_ROUND(17) TF_ROUND(29) TF_ROUND(16) TF_ROUND(24)
    x0 += TF_K1;        x1 += TF_K2 + 4u;
    TF_ROUND(13) TF_ROUND(15) TF_ROUND(26) TF_ROUND(6)
    x0 += TF_K2;        x1 += 0u + 5u;
#undef TF_ROUND
    return x0 ^ x1;
}

// bits -> uniform(tiny,1), matching jax _uniform in f32 exactly.
__device__ __forceinline__ float uniform32(uint32_t bits) {
    float f = __uint_as_float((bits >> 9) | 0x3f800000u) - 1.0f;
    return fmaxf(f, 1.17549435e-38f);
}

// Exact gumbel (matches XLA f32: precise logf == __nv_logf).
__device__ __forceinline__ float gumbel_exact(float u) {
    return -logf(-logf(u));
}

// One 2x2 window: fast gumbel-max with certified margin, exact fallback.
__device__ __forceinline__ float pool_window(float v0, float v1, float v2, float v3,
                                             float u0, float u1, float u2, float u3) {
    // Fast gumbel: t = -__logf(u) (MUFU.LG2+FMUL), g = -__logf(t).
    float t0 = -__logf(u0), t1 = -__logf(u1), t2 = -__logf(u2), t3 = -__logf(u3);
    float g0 = -__logf(t0), g1 = -__logf(t1), g2 = -__logf(t2), g3 = -__logf(t3);
    float s0 = v0 + g0, s1 = v1 + g1, s2 = v2 + g2, s3 = v3 + g3;

    // first-max scan (tie -> lower index; ties go slow-path anyway)
    float best = s0, second = -3.4e38f, val = v0;
    if (s1 > best) { second = best; best = s1; val = v1; } else second = s1;
    if (s2 > best) { second = best; best = s2; val = v2; }
    else if (s2 > second) second = s2;
    if (s3 > best) { second = best; best = s3; val = v3; }
    else if (s3 > second) second = s3;

    float min_t = fminf(fminf(t0, t1), fminf(t2, t3));
    float gabs  = fmaxf(fmaxf(fabsf(g0), fabsf(g1)), fmaxf(fabsf(g2), fabsf(g3)));
    // Per-value error bound of fast-vs-exact gumbel (conservative):
    //   |dg| <= 1e-6*(1+|g|) + 1e-6*max(1, 1/t)
    float E = 1e-6f * (1.0f + gabs)
            + 1e-6f * fmaxf(1.0f, __fdividef(1.0f, min_t));

    bool certain = (min_t >= 1e-3f) && (best - second > 2.0f * E);
    if (!certain) {
        // Bit-exact reference path (rare: ~0.4% of windows).
        float G0 = gumbel_exact(u0), G1 = gumbel_exact(u1);
        float G2 = gumbel_exact(u2), G3 = gumbel_exact(u3);
        float S0 = v0 + G0, S1 = v1 + G1, S2 = v2 + G2, S3 = v3 + G3;
        float B = S0; val = v0;
        if (S1 > B) { B = S1; val = v1; }
        if (S2 > B) { B = S2; val = v2; }
        if (S3 > B) { B = S3; val = v3; }
    }
    return val;
}

__global__ void __launch_bounds__(256)
stochpool_kernel(const float* __restrict__ x, float* __restrict__ out) {
    uint32_t i = blockIdx.x * 256u + threadIdx.x;  // grid covers range exactly

    // Thread i handles windows 2i, 2i+1 (adjacent in ow; OW=112 even).
    uint32_t owp = i % 56u;
    uint32_t t   = i / 56u;
    uint32_t oh  = t % 112u;
    uint32_t bc  = t / 112u;  // b*96 + c

    uint32_t in_base = (bc * 224u + 2u * oh) * 224u + 4u * owp;
    float4 r0 = *reinterpret_cast<const float4*>(x + in_base);
    float4 r1 = *reinterpret_cast<const float4*>(x + in_base + 224u);

    // Window w uses gumbel counters 4w..4w+3 -> this thread: 8i..8i+7.
    uint32_t cbase = 8u * i;
    float u[8];
#pragma unroll
    for (int k = 0; k < 8; k++)
        u[k] = uniform32(threefry_bits(cbase + (uint32_t)k));

    // window k-index = kh*2+kw -> (r.x, r.y of row0; r.x, r.y of row1)
    float o0 = pool_window(r0.x, r0.y, r1.x, r1.y, u[0], u[1], u[2], u[3]);
    float o1 = pool_window(r0.z, r0.w, r1.z, r1.w, u[4], u[5], u[6], u[7]);

    uint32_t out_base = (bc * 112u + oh) * 112u + 2u * owp;
    *reinterpret_cast<float2*>(out + out_base) = make_float2(o0, o1);
}

extern "C" void kernel_launch(void* const* d_in, const int* in_sizes, int n_in,
                              void* d_out, int out_size) {
    const float* x = (const float*)d_in[0];
    float* out = (float*)d_out;
    (void)in_sizes; (void)n_in; (void)out_size;
    stochpool_kernel<<<37632, 256>>>(x, out);
}